// round 5
// baseline (speedup 1.0000x reference)
#include <cuda_runtime.h>
#include <cstdint>

#define NB   32
#define NS   512
#define NBLK 128

// ------------------------- device scratch (no allocs allowed) ---------------
__device__ float g_xg[16384 * 3072];   // transposed: [(t*3H + n)*32 + b]
__device__ float g_y0[16384 * 512];
__device__ float g_y1[16384 * 1024];
__device__ float g_y2[16384 * 512];
__device__ float g_h [32 * 1024];      // k-interleaved: [(k>>2)*128 + b*4 + (k&3)]
__device__ float g_rh[32 * 1024];
// hierarchical monotonic barrier state (zero-init, never reset)
__device__ unsigned g_cnt[8 * 64];     // 8 group counters, 256B apart
__device__ unsigned g_sup;
__device__ unsigned g_rel;

__device__ __forceinline__ unsigned su32(const void* p) {
    return (unsigned)__cvta_generic_to_shared(p);
}
__device__ __forceinline__ float sigm(float x) {
    return 1.0f / (1.0f + __expf(-x));
}

// Hierarchical grid barrier, fence-free (acq_rel atomics; no CCTL.IVALL, so
// L1-resident weights survive). Monotonic counters; per-kernel bases are
// recovered exactly at entry: before this block's first arrival, its group
// counter can have at most 15 foreign arrivals (base = v - v%16), the super
// counter at most 7 (base = v - v%8), and the release counter none.
__device__ __forceinline__ void gbar(unsigned grp, unsigned i,
                                     unsigned bg, unsigned bs, unsigned br) {
    __syncthreads();
    if (threadIdx.x == 0) {
        unsigned old;
        asm volatile("atom.acq_rel.gpu.global.add.u32 %0, [%1], %2;"
                     : "=r"(old) : "l"(&g_cnt[grp * 64]), "r"(1u) : "memory");
        if (old == bg + i * 16u + 15u) {
            unsigned o2;
            asm volatile("atom.acq_rel.gpu.global.add.u32 %0, [%1], %2;"
                         : "=r"(o2) : "l"(&g_sup), "r"(1u) : "memory");
            if (o2 == bs + i * 8u + 7u) {
                asm volatile("red.release.gpu.global.add.u32 [%0], %1;"
                             :: "l"(&g_rel), "r"(1u) : "memory");
            }
        }
        const unsigned tgt = br + i + 1u;
        unsigned v;
        do {
            asm volatile("ld.acquire.gpu.global.u32 %0, [%1];"
                         : "=r"(v) : "l"(&g_rel) : "memory");
        } while ((int)(v - tgt) < 0);
    }
    __syncthreads();
}

__device__ __forceinline__ void mwait(unsigned mb, unsigned par) {
    asm volatile(
        "{\n\t.reg .pred P;\n"
        "LW_%=:\n\t"
        "mbarrier.try_wait.parity.shared.b64 P, [%0], %1;\n\t"
        "@!P bra LW_%=;\n\t}"
        :: "r"(mb), "r"(par) : "memory");
}
__device__ __forceinline__ void bulk_g2s(unsigned sdst, const void* gsrc,
                                         unsigned bytes, unsigned mb) {
    asm volatile(
        "cp.async.bulk.shared::cluster.global.mbarrier::complete_tx::bytes "
        "[%0], [%1], %2, [%3];"
        :: "r"(sdst), "l"(gsrc), "r"(bytes), "r"(mb) : "memory");
}
__device__ __forceinline__ void expect_tx(unsigned mb, unsigned bytes) {
    asm volatile("mbarrier.arrive.expect_tx.shared.b64 _, [%0], %1;"
                 :: "r"(mb), "r"(bytes) : "memory");
}

// ------------------------- GEMM: C = A[M,K] * B[N,K]^T + bias ---------------
// 128x128x16 tiles, double-buffered smem, 256 threads, 8x8 per thread.
template <bool RELU, bool TSTORE>
__global__ void __launch_bounds__(256, 2)
gemm_tn(const float* __restrict__ A, const float* __restrict__ B,
        const float* __restrict__ bias, float* __restrict__ C,
        int M, int N, int K)
{
    __shared__ float As[2][16][132];
    __shared__ float Bs[2][16][132];

    const int tid = threadIdx.x;
    const int tx  = tid & 15;
    const int ty  = tid >> 4;
    const int m0  = blockIdx.y * 128;
    const int n0  = blockIdx.x * 128;
    const int lr  = tid >> 2;
    const int lc  = (tid & 3) * 4;

    const float* Ap = A + (size_t)(m0 + lr) * K + lc;
    const float* Bp = B + (size_t)(n0 + lr) * K + lc;

    // prologue: tile 0 -> buffer 0
    float4 a0 = *(const float4*)Ap;
    float4 a1 = *(const float4*)(Ap + (size_t)64 * K);
    float4 b0 = *(const float4*)Bp;
    float4 b1 = *(const float4*)(Bp + (size_t)64 * K);
    As[0][lc + 0][lr] = a0.x; As[0][lc + 1][lr] = a0.y;
    As[0][lc + 2][lr] = a0.z; As[0][lc + 3][lr] = a0.w;
    As[0][lc + 0][lr + 64] = a1.x; As[0][lc + 1][lr + 64] = a1.y;
    As[0][lc + 2][lr + 64] = a1.z; As[0][lc + 3][lr + 64] = a1.w;
    Bs[0][lc + 0][lr] = b0.x; Bs[0][lc + 1][lr] = b0.y;
    Bs[0][lc + 2][lr] = b0.z; Bs[0][lc + 3][lr] = b0.w;
    Bs[0][lc + 0][lr + 64] = b1.x; Bs[0][lc + 1][lr + 64] = b1.y;
    Bs[0][lc + 2][lr + 64] = b1.z; Bs[0][lc + 3][lr + 64] = b1.w;
    __syncthreads();

    float acc[8][8] = {};
    const int nt = K / 16;

    for (int kt = 0; kt < nt; kt++) {
        const int cur = kt & 1;
        const bool more = (kt + 1 < nt);
        if (more) {
            const float* Ap2 = Ap + (kt + 1) * 16;
            const float* Bp2 = Bp + (kt + 1) * 16;
            a0 = *(const float4*)Ap2;
            a1 = *(const float4*)(Ap2 + (size_t)64 * K);
            b0 = *(const float4*)Bp2;
            b1 = *(const float4*)(Bp2 + (size_t)64 * K);
        }
        #pragma unroll
        for (int kk = 0; kk < 16; kk++) {
            float4 av0 = *(const float4*)&As[cur][kk][ty * 8];
            float4 av1 = *(const float4*)&As[cur][kk][ty * 8 + 4];
            float4 bv0 = *(const float4*)&Bs[cur][kk][tx * 8];
            float4 bv1 = *(const float4*)&Bs[cur][kk][tx * 8 + 4];
            const float a[8] = {av0.x, av0.y, av0.z, av0.w, av1.x, av1.y, av1.z, av1.w};
            const float b[8] = {bv0.x, bv0.y, bv0.z, bv0.w, bv1.x, bv1.y, bv1.z, bv1.w};
            #pragma unroll
            for (int i = 0; i < 8; i++)
                #pragma unroll
                for (int j = 0; j < 8; j++)
                    acc[i][j] = fmaf(a[i], b[j], acc[i][j]);
        }
        if (more) {
            const int nxt = cur ^ 1;
            __syncthreads();
            As[nxt][lc + 0][lr] = a0.x; As[nxt][lc + 1][lr] = a0.y;
            As[nxt][lc + 2][lr] = a0.z; As[nxt][lc + 3][lr] = a0.w;
            As[nxt][lc + 0][lr + 64] = a1.x; As[nxt][lc + 1][lr + 64] = a1.y;
            As[nxt][lc + 2][lr + 64] = a1.z; As[nxt][lc + 3][lr + 64] = a1.w;
            Bs[nxt][lc + 0][lr] = b0.x; Bs[nxt][lc + 1][lr] = b0.y;
            Bs[nxt][lc + 2][lr] = b0.z; Bs[nxt][lc + 3][lr] = b0.w;
            Bs[nxt][lc + 0][lr + 64] = b1.x; Bs[nxt][lc + 1][lr + 64] = b1.y;
            Bs[nxt][lc + 2][lr + 64] = b1.z; Bs[nxt][lc + 3][lr + 64] = b1.w;
            __syncthreads();
        }
    }

    float bv[8];
    #pragma unroll
    for (int j = 0; j < 8; j++) bv[j] = bias[n0 + tx * 8 + j];

    #pragma unroll
    for (int i = 0; i < 8; i++) {
        const int m = m0 + ty * 8 + i;
        if (TSTORE) {
            const int t = m & (NS - 1);
            const int b = m >> 9;
            #pragma unroll
            for (int j = 0; j < 8; j++) {
                const int n = n0 + tx * 8 + j;
                C[((size_t)t * N + n) * 32 + b] = acc[i][j] + bv[j];
            }
        } else {
            float4 v0, v1;
            v0.x = acc[i][0] + bv[0]; v0.y = acc[i][1] + bv[1];
            v0.z = acc[i][2] + bv[2]; v0.w = acc[i][3] + bv[3];
            v1.x = acc[i][4] + bv[4]; v1.y = acc[i][5] + bv[5];
            v1.z = acc[i][6] + bv[6]; v1.w = acc[i][7] + bv[7];
            if (RELU) {
                v0.x = fmaxf(v0.x, 0.f); v0.y = fmaxf(v0.y, 0.f);
                v0.z = fmaxf(v0.z, 0.f); v0.w = fmaxf(v0.w, 0.f);
                v1.x = fmaxf(v1.x, 0.f); v1.y = fmaxf(v1.y, 0.f);
                v1.z = fmaxf(v1.z, 0.f); v1.w = fmaxf(v1.w, 0.f);
            }
            *(float4*)(C + (size_t)m * N + n0 + tx * 8)     = v0;
            *(float4*)(C + (size_t)m * N + n0 + tx * 8 + 4) = v1;
        }
    }
}

// ------------------------- persistent GRU scan ------------------------------
// 128 blocks x 256 threads. lane = batch. Block owns JB contiguous columns.
// Warps = (col-group wq) x (K-slice kh); each LDS.128 of state feeds 32 FFMA.
// K-slice partials reduced via smem; warp w finalizes column J0+w, keeping
// z and h_old in registers across phases. State broadcast in S chunks via
// cp.async.bulk (chunk kh -> mbar[kh]) so copy overlaps compute.
template <int H>
__global__ void __launch_bounds__(256, 1)
gru_scan(const float* __restrict__ xg, const float* __restrict__ Wh,
         const float* __restrict__ h0, float* __restrict__ y)
{
    constexpr int JB  = (H == 1024) ? 8 : 4;
    constexpr int GQ  = (H == 1024) ? 2 : 1;   // column groups
    constexpr int S   = 8 / GQ;                // K-slices (4 or 8)
    constexpr int JT  = JB / GQ;               // 4 columns per warp
    constexpr int K4  = H / 4;
    constexpr int K4S = K4 / S;                // 64 or 16
    constexpr unsigned STATE_B = 32u * H * 4u;
    constexpr unsigned CHUNK_B = STATE_B / S;

    extern __shared__ float sm[];
    float* sm_state = sm;                          // [32*H]
    float* sm_red   = sm + 32 * H;                 // [JB*2*S*32]
    float* sm_yb    = sm_red + JB * 2 * S * 32;    // [JB*32]
    __shared__ __align__(8) unsigned long long mbar[S];

    const int tid   = threadIdx.x;
    const int lane  = tid & 31;
    const int w     = tid >> 5;
    const int wq    = w % GQ;
    const int kh    = w / GQ;
    const int J0    = blockIdx.x * JB;
    const int jbase = J0 + wq * JT;
    const unsigned grp = blockIdx.x & 7;
    const bool fin  = (w < JB);
    const int  jfin = J0 + w;
    const unsigned mbk = su32(&mbar[kh]);

    unsigned bg = 0, bs = 0, br = 0;
    if (tid == 0) {
        unsigned v = *(volatile unsigned*)&g_cnt[grp * 64]; bg = v - (v & 15u);
        v = *(volatile unsigned*)&g_sup;                    bs = v - (v & 7u);
        br = *(volatile unsigned*)&g_rel;
        #pragma unroll
        for (int c = 0; c < S; c++)
            asm volatile("mbarrier.init.shared.b64 [%0], 1;"
                         :: "r"(su32(&mbar[c])) : "memory");
    }
    __syncthreads();

    // init h = broadcast(h0) in interleaved layout (L2-coherent stores)
    for (int idx = blockIdx.x * 256 + tid; idx < 32 * H; idx += NBLK * 256) {
        const int k = idx >> 5, b = idx & 31;
        __stcg(&g_h[(k >> 2) * 128 + b * 4 + (k & 3)], h0[k]);
    }
    unsigned bi = 0;
    gbar(grp, bi, bg, bs, br); bi++;
    if (tid == 0) {
        asm volatile("fence.proxy.async;" ::: "memory");
        #pragma unroll
        for (int c = 0; c < S; c++) {
            const unsigned mb = su32(&mbar[c]);
            expect_tx(mb, CHUNK_B);
            bulk_g2s(su32(sm_state) + c * CHUNK_B,
                     (const char*)g_h + c * CHUNK_B, CHUNK_B, mb);
        }
    }

    const float4* W4  = (const float4*)Wh;
    const float4* hs4 = (const float4*)sm_state;
    unsigned par = 0;
    float z_r = 0.f, h_r = 0.f;

    for (int t = 0; t < NS; t++) {
        // ================= phase 1: r, z =================
        float xr = 0.f, xz = 0.f;
        if (fin) {
            xr = xg[((size_t)t * 3 * H + jfin) * 32 + lane];
            xz = xg[((size_t)t * 3 * H + H + jfin) * 32 + lane];
        }
        mwait(mbk, par); par ^= 1;                  // my h chunk staged

        float ar[JT] = {}, az[JT] = {};
        {
            const float4* hp = hs4 + (size_t)kh * K4S * 32 + lane;
            #pragma unroll 4
            for (int k4 = 0; k4 < K4S; k4++) {
                const float4 h4 = hp[(size_t)k4 * 32];
                #pragma unroll
                for (int i = 0; i < JT; i++) {
                    const float4 wr = __ldg(W4 + (size_t)(jbase + i) * K4 + kh * K4S + k4);
                    const float4 wz = __ldg(W4 + ((size_t)H + jbase + i) * K4 + kh * K4S + k4);
                    ar[i] = fmaf(h4.x, wr.x, fmaf(h4.y, wr.y,
                            fmaf(h4.z, wr.z, fmaf(h4.w, wr.w, ar[i]))));
                    az[i] = fmaf(h4.x, wz.x, fmaf(h4.y, wz.y,
                            fmaf(h4.z, wz.z, fmaf(h4.w, wz.w, az[i]))));
                }
            }
        }
        #pragma unroll
        for (int i = 0; i < JT; i++) {
            const int jj = wq * JT + i;
            sm_red[((jj * 2 + 0) * S + kh) * 32 + lane] = ar[i];
            sm_red[((jj * 2 + 1) * S + kh) * 32 + lane] = az[i];
        }
        __syncthreads();                            // all chunks + partials done
        if (fin) {
            float sr = xr, sz = xz;
            #pragma unroll
            for (int c = 0; c < S; c++) {
                sr += sm_red[((w * 2 + 0) * S + c) * 32 + lane];
                sz += sm_red[((w * 2 + 1) * S + c) * 32 + lane];
            }
            const float r = sigm(sr);
            z_r = sigm(sz);
            h_r = sm_state[(jfin >> 2) * 128 + lane * 4 + (jfin & 3)];
            __stcg(&g_rh[(jfin >> 2) * 128 + lane * 4 + (jfin & 3)], r * h_r);
        }
        gbar(grp, bi, bg, bs, br); bi++;            // rh globally complete
        if (tid == 0) {
            asm volatile("fence.proxy.async;" ::: "memory");
            #pragma unroll
            for (int c = 0; c < S; c++) {
                const unsigned mb = su32(&mbar[c]);
                expect_tx(mb, CHUNK_B);
                bulk_g2s(su32(sm_state) + c * CHUNK_B,
                         (const char*)g_rh + c * CHUNK_B, CHUNK_B, mb);
            }
        }

        // ================= phase 2: n + update =================
        float xn = 0.f;
        if (fin) xn = xg[((size_t)t * 3 * H + 2 * H + jfin) * 32 + lane];
        mwait(mbk, par); par ^= 1;                  // my rh chunk staged

        float an[JT] = {};
        {
            const float4* rp = hs4 + (size_t)kh * K4S * 32 + lane;
            #pragma unroll 4
            for (int k4 = 0; k4 < K4S; k4++) {
                const float4 r4 = rp[(size_t)k4 * 32];
                #pragma unroll
                for (int i = 0; i < JT; i++) {
                    const float4 wn = __ldg(W4 + ((size_t)2 * H + jbase + i) * K4 + kh * K4S + k4);
                    an[i] = fmaf(r4.x, wn.x, fmaf(r4.y, wn.y,
                            fmaf(r4.z, wn.z, fmaf(r4.w, wn.w, an[i]))));
                }
            }
        }
        #pragma unroll
        for (int i = 0; i < JT; i++)
            sm_red[((wq * JT + i) * S + kh) * 32 + lane] = an[i];
        __syncthreads();
        if (fin) {
            float sn = xn;
            #pragma unroll
            for (int c = 0; c < S; c++) sn += sm_red[(w * S + c) * 32 + lane];
            const float n    = tanhf(sn);
            const float hnew = fmaf(z_r, n - h_r, h_r);   // (1-z)h + z n
            __stcg(&g_h[(jfin >> 2) * 128 + lane * 4 + (jfin & 3)], hnew);
            sm_yb[w * 32 + lane] = hnew;
        }
        gbar(grp, bi, bg, bs, br); bi++;            // h globally complete
        if (tid == 0 && t + 1 < NS) {
            asm volatile("fence.proxy.async;" ::: "memory");
            #pragma unroll
            for (int c = 0; c < S; c++) {
                const unsigned mb = su32(&mbar[c]);
                expect_tx(mb, CHUNK_B);
                bulk_g2s(su32(sm_state) + c * CHUNK_B,
                         (const char*)g_h + c * CHUNK_B, CHUNK_B, mb);
            }
        }
        // coalesced-ish y store from the bounce buffer (overlaps next copy)
        for (int idx = tid; idx < 32 * JB; idx += 256) {
            const int b = idx / JB, jj = idx % JB;
            y[((size_t)(b * NS + t)) * H + J0 + jj] = sm_yb[jj * 32 + b];
        }
    }
}

// ------------------------- launch ------------------------------------------
extern "C" void kernel_launch(void* const* d_in, const int* in_sizes, int n_in,
                              void* d_out, int out_size)
{
    (void)in_sizes; (void)n_in; (void)out_size;
    const float* x   = (const float*)d_in[0];
    const float* Wi0 = (const float*)d_in[1];
    const float* Wh0 = (const float*)d_in[2];
    const float* bh0 = (const float*)d_in[3];
    const float* h00 = (const float*)d_in[4];
    const float* Wi1 = (const float*)d_in[5];
    const float* Wh1 = (const float*)d_in[6];
    const float* bh1 = (const float*)d_in[7];
    const float* h01 = (const float*)d_in[8];
    const float* Wi2 = (const float*)d_in[9];
    const float* Wh2 = (const float*)d_in[10];
    const float* bh2 = (const float*)d_in[11];
    const float* h02 = (const float*)d_in[12];
    const float* Wo  = (const float*)d_in[13];
    const float* bo  = (const float*)d_in[14];
    float* out = (float*)d_out;

    float *xg_p, *y0_p, *y1_p, *y2_p;
    cudaGetSymbolAddress((void**)&xg_p, g_xg);
    cudaGetSymbolAddress((void**)&y0_p, g_y0);
    cudaGetSymbolAddress((void**)&y1_p, g_y1);
    cudaGetSymbolAddress((void**)&y2_p, g_y2);

    const int SMEM512  = 32 * 512 * 4  + 4 * 2 * 8 * 32 * 4 + 4 * 32 * 4;   // 74240
    const int SMEM1024 = 32 * 1024 * 4 + 8 * 2 * 4 * 32 * 4 + 8 * 32 * 4;   // 140288
    cudaFuncSetAttribute(gru_scan<512>,  cudaFuncAttributeMaxDynamicSharedMemorySize, SMEM512);
    cudaFuncSetAttribute(gru_scan<1024>, cudaFuncAttributeMaxDynamicSharedMemorySize, SMEM1024);

    const int M = NB * NS;  // 16384

    // layer 0: 256 -> 512
    gemm_tn<false, true ><<<dim3(1536 / 128, M / 128), 256>>>(x, Wi0, bh0, xg_p, M, 1536, 256);
    gru_scan<512><<<NBLK, 256, SMEM512>>>(xg_p, Wh0, h00, y0_p);
    // layer 1: 512 -> 1024
    gemm_tn<false, true ><<<dim3(3072 / 128, M / 128), 256>>>(y0_p, Wi1, bh1, xg_p, M, 3072, 512);
    gru_scan<1024><<<NBLK, 256, SMEM1024>>>(xg_p, Wh1, h01, y1_p);
    // layer 2: 1024 -> 512
    gemm_tn<false, true ><<<dim3(1536 / 128, M / 128), 256>>>(y1_p, Wi2, bh2, xg_p, M, 1536, 1024);
    gru_scan<512><<<NBLK, 256, SMEM512>>>(xg_p, Wh2, h02, y2_p);
    // output head: 512 -> 256, ReLU, row-major
    gemm_tn<true, false><<<dim3(256 / 128, M / 128), 256>>>(y2_p, Wo, bo, out, M, 256, 512);
}